// round 1
// baseline (speedup 1.0000x reference)
#include <cuda_runtime.h>
#include <math.h>

#define DN   512
#define DQv  256
#define NPG  4096
#define NB   64
#define MI   8
#define NTOT (NB*NPG)
#define KSEL 1229   // ceil(0.3 * 4096)

#define BM 64
#define BK 16

// scratch: scores[B][M][NPG]  (8 MB) — fully overwritten each call
__device__ float g_scores[NB * MI * NPG];

__device__ __forceinline__ unsigned long long fma2(unsigned long long a,
                                                   unsigned long long b,
                                                   unsigned long long c) {
    unsigned long long d;
    asm("fma.rn.f32x2 %0, %1, %2, %3;" : "=l"(d) : "l"(a), "l"(b), "l"(c));
    return d;
}

// ---------------------------------------------------------------------------
// Kernel 1: h = gelu(x@Wn + bn) fused with scores[b][m][node] = h . u[m][b]
// grid = NTOT/BM = 4096 blocks, 256 threads. BM=64 rows, full DQ=256 cols.
// ---------------------------------------------------------------------------
__global__ void __launch_bounds__(256, 2)
gemm_gelu_score(const float* __restrict__ x, const float* __restrict__ u,
                const float* __restrict__ Wn, const float* __restrict__ bn)
{
    __shared__ float As2[BK][2 * BM];   // A values duplicated (v,v) -> direct f32x2 operand
    __shared__ float Bs[BK][DQv];
    __shared__ float Us[MI][DQv];

    const int tid      = threadIdx.x;
    const int rowBase  = blockIdx.x * BM;
    const int b        = rowBase >> 12;        // NPG = 4096
    const int nodeBase = rowBase & (NPG - 1);

    // load this graph's 8 instruction vectors: u[m][b][c]
    for (int i = tid; i < MI * DQv; i += 256) {
        int m = i >> 8, c = i & 255;
        Us[m][c] = u[(m * NB + b) * DQv + c];
    }

    const int warp = tid >> 5, lane = tid & 31;
    const int r0 = warp * 8;        // 8 warps x 8 rows = 64 rows
    const int c0 = lane * 8;        // 32 lanes x 8 cols = 256 cols

    // A tile loader: thread loads float4 of x[rowBase + tid/4][(tid%4)*4 + ...]
    const int arow  = tid >> 2;
    const int acol4 = (tid & 3) << 2;
    const float* Ap = x + (size_t)(rowBase + arow) * DN + acol4;

    // B tile loader: 4 iterations of float4, fully coalesced
    const int bk = tid >> 6;
    const int bc = (tid & 63) << 2;

    unsigned long long acc[8][4];
    #pragma unroll
    for (int r = 0; r < 8; ++r)
        #pragma unroll
        for (int c = 0; c < 4; ++c) acc[r][c] = 0ULL;   // packed (0.0f, 0.0f)

    for (int kt = 0; kt < DN / BK; ++kt) {
        float4 av = *(const float4*)(Ap + kt * BK);
        As2[acol4 + 0][2 * arow] = av.x; As2[acol4 + 0][2 * arow + 1] = av.x;
        As2[acol4 + 1][2 * arow] = av.y; As2[acol4 + 1][2 * arow + 1] = av.y;
        As2[acol4 + 2][2 * arow] = av.z; As2[acol4 + 2][2 * arow + 1] = av.z;
        As2[acol4 + 3][2 * arow] = av.w; As2[acol4 + 3][2 * arow + 1] = av.w;
        #pragma unroll
        for (int i = 0; i < 4; ++i) {
            int kk = bk + (i << 2);
            *(float4*)&Bs[kk][bc] =
                *(const float4*)(Wn + (size_t)(kt * BK + kk) * DQv + bc);
        }
        __syncthreads();

        #pragma unroll
        for (int k = 0; k < BK; ++k) {
            unsigned long long b2[4];
            ulonglong2 t0 = *(const ulonglong2*)&Bs[k][c0];
            ulonglong2 t1 = *(const ulonglong2*)&Bs[k][c0 + 4];
            b2[0] = t0.x; b2[1] = t0.y; b2[2] = t1.x; b2[3] = t1.y;
            #pragma unroll
            for (int r = 0; r < 8; ++r) {
                unsigned long long a2 =
                    *(const unsigned long long*)&As2[k][2 * (r0 + r)];
                acc[r][0] = fma2(a2, b2[0], acc[r][0]);
                acc[r][1] = fma2(a2, b2[1], acc[r][1]);
                acc[r][2] = fma2(a2, b2[2], acc[r][2]);
                acc[r][3] = fma2(a2, b2[3], acc[r][3]);
            }
        }
        __syncthreads();
    }

    float bnv[8];
    *(float4*)&bnv[0] = *(const float4*)(bn + c0);
    *(float4*)&bnv[4] = *(const float4*)(bn + c0 + 4);

    #pragma unroll
    for (int r = 0; r < 8; ++r) {
        float h[8];
        #pragma unroll
        for (int c2 = 0; c2 < 4; ++c2) {
            h[2 * c2]     = __uint_as_float((unsigned int)(acc[r][c2]));
            h[2 * c2 + 1] = __uint_as_float((unsigned int)(acc[r][c2] >> 32));
        }
        #pragma unroll
        for (int c = 0; c < 8; ++c) {
            float v = h[c] + bnv[c];
            // exact GELU: v * 0.5 * (1 + erf(v / sqrt(2)))
            h[c] = 0.5f * v * (1.0f + erff(v * 0.70710678118654752f));
        }
        const int node = nodeBase + r0 + r;
        #pragma unroll
        for (int m = 0; m < MI; ++m) {
            float p = 0.f;
            #pragma unroll
            for (int c = 0; c < 8; ++c) p = fmaf(h[c], Us[m][c0 + c], p);
            #pragma unroll
            for (int off = 16; off > 0; off >>= 1)
                p += __shfl_down_sync(0xffffffffu, p, off);
            if (lane == 0)
                g_scores[(b * MI + m) * NPG + node] = p;
        }
    }
}

// ---------------------------------------------------------------------------
// Kernel 2: per graph — softmax over n per (m), gate = sum_m attn,
//           exact K-th largest via in-smem bitonic sort, mask = gate >= kth.
// grid = 64 blocks, 512 threads. Fully deterministic (no float atomics).
// ---------------------------------------------------------------------------
__global__ void __launch_bounds__(512)
gate_topk(float* __restrict__ out)
{
    __shared__ float gate[NPG];   // 16 KB
    __shared__ float buf[NPG];    // 16 KB
    __shared__ float red_a[16];
    __shared__ float red_b[16];

    const int b = blockIdx.x;
    const int tid = threadIdx.x;
    const int lane = tid & 31, wid = tid >> 5;

    for (int i = tid; i < NPG; i += 512) gate[i] = 0.f;

    for (int m = 0; m < MI; ++m) {
        const float* s = g_scores + (b * MI + m) * NPG;
        float v[8];
        float mx = -3.4e38f;
        #pragma unroll
        for (int i = 0; i < 8; ++i) {
            v[i] = s[(i << 9) + tid];
            mx = fmaxf(mx, v[i]);
        }
        #pragma unroll
        for (int off = 16; off > 0; off >>= 1)
            mx = fmaxf(mx, __shfl_xor_sync(0xffffffffu, mx, off));
        if (lane == 0) red_a[wid] = mx;
        __syncthreads();
        mx = red_a[0];
        #pragma unroll
        for (int i = 1; i < 16; ++i) mx = fmaxf(mx, red_a[i]);

        float e[8];
        float se = 0.f;
        #pragma unroll
        for (int i = 0; i < 8; ++i) { e[i] = expf(v[i] - mx); se += e[i]; }
        #pragma unroll
        for (int off = 16; off > 0; off >>= 1)
            se += __shfl_xor_sync(0xffffffffu, se, off);
        if (lane == 0) red_b[wid] = se;
        __syncthreads();
        float tot = 0.f;
        #pragma unroll
        for (int i = 0; i < 16; ++i) tot += red_b[i];

        #pragma unroll
        for (int i = 0; i < 8; ++i)
            gate[(i << 9) + tid] += e[i] / tot;   // per-thread-private slots, no race
        __syncthreads();   // protect red_a reuse next m
    }

    for (int i = tid; i < NPG; i += 512) buf[i] = gate[i];
    __syncthreads();

    // bitonic sort ascending (4096 elements, all finite)
    for (int k = 2; k <= NPG; k <<= 1) {
        for (int j = k >> 1; j > 0; j >>= 1) {
            for (int i = tid; i < NPG; i += 512) {
                int l = i ^ j;
                if (l > i) {
                    float a0 = buf[i], a1 = buf[l];
                    if (((i & k) == 0) == (a0 > a1)) { buf[i] = a1; buf[l] = a0; }
                }
            }
            __syncthreads();
        }
    }

    const float kth = buf[NPG - KSEL];   // K-th largest
    float* o = out + b * NPG;
    for (int i = tid; i < NPG; i += 512)
        o[i] = (gate[i] >= kth) ? 1.0f : 0.0f;
}

// ---------------------------------------------------------------------------
extern "C" void kernel_launch(void* const* d_in, const int* in_sizes, int n_in,
                              void* d_out, int out_size) {
    const float* x  = (const float*)d_in[0];
    const float* u  = (const float*)d_in[1];
    const float* Wn = (const float*)d_in[2];
    const float* bn = (const float*)d_in[3];
    // d_in[4] = batch (sorted equal segments -> implicit), d_in[5] = edge_index (unused)

    gemm_gelu_score<<<NTOT / BM, 256>>>(x, u, Wn, bn);
    gate_topk<<<NB, 512>>>((float*)d_out);
}